// round 12
// baseline (speedup 1.0000x reference)
#include <cuda_runtime.h>
#include <cstdint>

#define MAX_SPIKE_TIME 100000.0f

// Problem constants (from reference setup_inputs)
static constexpr int B_SIZE   = 64;
static constexpr int IN_SIZE  = 1024;
static constexpr int NP1      = IN_SIZE + 1;   // 1025 (with appended 1.0)
static constexpr int OUT_SIZE = 512;
static constexpr int NSORT    = 1024;          // sort only the 1024 real inputs
static constexpr int THREADS  = 512;           // 256 j-lanes x 2 k-chunks
static constexpr int J_PER_BLOCK = 256;        // outputs per block (2 blocks per batch)
static constexpr int XR       = 16;            // xi register-ring size (LDS distance 16)
static constexpr int PD       = 8;             // weight LDG prefetch distance
static constexpr int CHUNK0   = 672;           // k-split point (42*16)
static constexpr int XI_SIZE  = NP1 + XR + 4;  // 1045: sorted array + sentinel/overrun pad

// Scan sorted positions [k0, k0+iters) for one output column.
// GATES=false: accumulate only (prefix pass; sequential order => accumulators
// bit-identical to the gated pass). GATES=true: validity gates + FIRST-valid
// capture. Since valid candidates are bracketed by ascending xs, the first
// valid candidate is the global min — no running-min compare needed.
// Cross-multiplied gate comparisons (denom > 0 always). Requires k0 % 16 == 0.
template <bool GATES>
__device__ __forceinline__ void scan_range(const float2* __restrict__ xi,
                                           const char* __restrict__ Wj,
                                           int k0, int iters,
                                           float& w_cum, float& wi_cum,
                                           float& fnum, float& fden, bool& found)
{
    float2 xr[XR];                       // xi[k .. k+15] register ring
    #pragma unroll
    for (int p = 0; p < XR; ++p) xr[p] = xi[k0 + p];
    float wbuf[PD];                      // weights in flight, distance PD
    #pragma unroll
    for (int p = 0; p < PD; ++p) {
        unsigned off = __float_as_uint(xr[p].y);
        wbuf[p] = __ldg((const float*)(Wj + off));
    }
    float2 cur = xr[0];

    #pragma unroll 1
    for (int kb = 0; kb < iters; kb += XR) {
        #pragma unroll
        for (int v = 0; v < XR; ++v) {
            const int k = k0 + kb + v;
            const int u = v & (PD - 1);
            float2 nxt = xr[(v + 1) & (XR - 1)];   // xi[k+1], in registers
            float  w   = wbuf[u];                   // W[row(xi[k])], issued k-PD
            // prefetch weight for iter k+PD; address LDS'd >= PD-1 iters ago
            unsigned poff = __float_as_uint(xr[(v + PD) & (XR - 1)].y);
            xr[v] = xi[k + XR];                     // ring refill (used k+XR-1)
            wbuf[u] = __ldg((const float*)(Wj + poff));

            // mirror reference: ws*xs (unfused) then cumsum
            wi_cum = __fadd_rn(wi_cum, __fmul_rn(w, cur.x));
            w_cum  = __fadd_rn(w_cum, w);

            if (GATES) {
                float denom = fmaxf(w_cum - 1.0f, 1e-10f);
                // cand >= xs[k]  <=> wi_cum >= xs[k]*denom ; upper gate likewise
                bool valid = (w_cum >= 1.0f)
                           & (wi_cum >= __fmul_rn(cur.x, denom))
                           & (wi_cum <= __fmul_rn(nxt.x, denom));
                bool take = valid & !found;
                if (take) { fnum = wi_cum; fden = denom; }
                found = found | valid;
            }
            cur = nxt;
        }
    }
}

__global__ __launch_bounds__(THREADS, 1)
void snn_layer_kernel(const float* __restrict__ layer_in,
                      const float* __restrict__ weight,
                      const float* __restrict__ delay,
                      float* __restrict__ out)
{
    __shared__ unsigned long long sbuf[NSORT];    // 8 KB sort buffer
    __shared__ __align__(16) float2 xi[XI_SIZE];  // (sorted value, byte-offset bits)
    __shared__ float2 cbest[J_PER_BLOCK];         // chunk0 result: (num, den or -1)
    __shared__ int s_pos;                         // insertion position of appended 1.0

    const int tid   = threadIdx.x;
    const int jl    = tid & (J_PER_BLOCK - 1);    // j lane within block
    const int chunk = tid >> 8;                   // 0: k in [0,672)  1: k in [672,1025)
    const int b     = blockIdx.x >> 1;
    const int j     = (blockIdx.x & 1) * J_PER_BLOCK + jl;

    if (tid == 0) s_pos = 0;
    __syncthreads();

    // ---- Phase 1: keys = (float_bits(x) << 32) | (index << 11) ----
    // x >= 0 so float-bit order == value order; (index<<11) keeps jnp.argsort's
    // stable tie-break and directly encodes the weight-row byte offset.
    // count(x <= 1.0) = stable insertion position of appended (1.0, idx=1024).
    const float* lin = layer_in + (size_t)b * IN_SIZE;
    int cnt = 0;
    for (int i = tid; i < NSORT; i += THREADS) {
        float d  = delay[i];
        float xv = lin[i] * expf(fmaxf(d, 0.0f));   // accurate exp, matches jnp
        cnt += (xv <= 1.0f);
        sbuf[i] = ((unsigned long long)__float_as_uint(xv) << 32)
                | (unsigned)(i << 11);
    }
    if (cnt) atomicAdd(&s_pos, cnt);
    __syncthreads();

    // ---- Phase 2: bitonic sort (ascending), 512 threads over 1024 keys ----
    for (int k = 2; k <= NSORT; k <<= 1) {
        for (int jj = k >> 1; jj > 0; jj >>= 1) {
            for (int i = tid; i < NSORT; i += THREADS) {
                int ixj = i ^ jj;
                if (ixj > i) {
                    unsigned long long a = sbuf[i];
                    unsigned long long c = sbuf[ixj];
                    bool up = ((i & k) == 0);
                    if ((a > c) == up) { sbuf[i] = c; sbuf[ixj] = a; }
                }
            }
            __syncthreads();
        }
    }

    // ---- Phase 3: unpack with insertion of (1.0, idx=1024) + pad ----
    const int pos = s_pos;
    for (int p = tid; p < NSORT; p += THREADS) {
        unsigned long long key = sbuf[p];
        int dest = p + (p >= pos);
        xi[dest] = make_float2(__uint_as_float((unsigned)(key >> 32)),
                               __uint_as_float((unsigned)(key & 0xffffffffu)));
    }
    if (tid == 0) xi[pos] = make_float2(1.0f, __uint_as_float(1024u << 11));
    if (NP1 + tid < XI_SIZE) xi[NP1 + tid] = make_float2(MAX_SPIKE_TIME, 0.0f);
    __syncthreads();

    // ---- Phase 4: k-split scan, first-valid capture per chunk ----
    const char* Wj = (const char*)(weight + j);
    float w_cum = 0.0f, wi_cum = 0.0f;
    float fnum = MAX_SPIKE_TIME, fden = 1.0f;
    bool  found = false;

    if (chunk == 0) {
        // gated scan over [0, CHUNK0)
        scan_range<true>(xi, Wj, 0, CHUNK0, w_cum, wi_cum, fnum, fden, found);
        // publish: den sign encodes "found" (den > 0 always when found)
        cbest[jl] = make_float2(fnum, found ? fden : -1.0f);
        __syncthreads();
    } else {
        // epilogue weight (k=1024) prefetched now, hidden behind the scan
        unsigned off1024 = __float_as_uint(xi[IN_SIZE].y);
        float we = __ldg((const float*)(Wj + off1024));

        // prefix over [0, CHUNK0): sequential order => accumulators
        // bit-identical to chunk0's finals; then gated scan over [CHUNK0, 1024)
        scan_range<false>(xi, Wj, 0, CHUNK0, w_cum, wi_cum, fnum, fden, found);
        scan_range<true>(xi, Wj, CHUNK0, IN_SIZE - CHUNK0, w_cum, wi_cum, fnum, fden, found);

        // epilogue: k = 1024 (sentinel gate on the right)
        {
            float2 cur = xi[IN_SIZE];
            float2 nxt = xi[NP1];
            wi_cum = __fadd_rn(wi_cum, __fmul_rn(we, cur.x));
            w_cum  = __fadd_rn(w_cum, we);
            float denom = fmaxf(w_cum - 1.0f, 1e-10f);
            bool valid = (w_cum >= 1.0f)
                       & (wi_cum >= __fmul_rn(cur.x, denom))
                       & (wi_cum <= __fmul_rn(nxt.x, denom));
            bool take = valid & !found;
            if (take) { fnum = wi_cum; fden = denom; }
            found = found | valid;
        }

        __syncthreads();

        // merge: global first-valid = chunk0's (earlier k) if found, else ours
        float2 cb = cbest[jl];
        float num, den;
        if (cb.y > 0.0f)      { num = cb.x; den = cb.y; }
        else if (found)       { num = fnum; den = fden; }
        else                  { num = MAX_SPIKE_TIME; den = 1.0f; }

        out[(size_t)b * OUT_SIZE + j] = num / den;   // one exact IEEE division
    }
}

extern "C" void kernel_launch(void* const* d_in, const int* in_sizes, int n_in,
                              void* d_out, int out_size)
{
    const float* layer_in = (const float*)d_in[0];  // (64, 1024)
    const float* weight   = (const float*)d_in[1];  // (1025, 512)
    const float* delay    = (const float*)d_in[2];  // (1024,)
    float* out = (float*)d_out;                     // (64, 512)

    dim3 grid(B_SIZE * (OUT_SIZE / J_PER_BLOCK));   // 128 blocks
    dim3 block(THREADS);                            // 512 threads
    snn_layer_kernel<<<grid, block>>>(layer_in, weight, delay, out);
}

// round 13
// speedup vs baseline: 1.2202x; 1.2202x over previous
#include <cuda_runtime.h>
#include <cstdint>

#define MAX_SPIKE_TIME 100000.0f

// Problem constants (from reference setup_inputs)
static constexpr int B_SIZE   = 64;
static constexpr int IN_SIZE  = 1024;
static constexpr int NP1      = IN_SIZE + 1;   // 1025 (with appended 1.0)
static constexpr int OUT_SIZE = 512;
static constexpr int NSORT    = 1024;          // sort only the 1024 real inputs
static constexpr int THREADS  = 512;           // 256 j-lanes x 2 k-chunks
static constexpr int J_PER_BLOCK = 256;        // outputs per block (2 blocks per batch)
static constexpr int XR       = 16;            // xi register-ring size (LDS distance 16)
static constexpr int PD       = 8;             // weight LDG prefetch distance
static constexpr int NB       = 4;             // best-fraction slots
static constexpr int CHUNK0   = 672;           // k-split point (42*16)
static constexpr int XI_SIZE  = NP1 + XR + 7;  // sorted array + sentinel/overrun pad

// Scan sorted positions [k0, k0+iters) for one output column.
// GATES=false: accumulate only (prefix pass; sequential order => accumulators
// bit-identical to the gated pass). GATES=true: validity gates + slot-private
// fraction min (cross-multiplied; denom > 0 always). Requires k0 % 16 == 0.
// Ring refill: two dead slots (v-1, v) per odd iteration via one LDS.128.
template <bool GATES>
__device__ __forceinline__ void scan_range(const float2* __restrict__ xi,
                                           const char* __restrict__ Wj,
                                           int k0, int iters,
                                           float& w_cum, float& wi_cum,
                                           float* bnum, float* bden)
{
    float2 xr[XR];                       // xi[k .. k+15] register ring
    #pragma unroll
    for (int p = 0; p < XR; p += 2) {    // k0 % 16 == 0 -> 16B-aligned pairs
        float4 t = *reinterpret_cast<const float4*>(&xi[k0 + p]);
        xr[p]     = make_float2(t.x, t.y);
        xr[p + 1] = make_float2(t.z, t.w);
    }
    float wbuf[PD];                      // weights in flight, distance PD
    #pragma unroll
    for (int p = 0; p < PD; ++p) {
        unsigned off = __float_as_uint(xr[p].y);
        wbuf[p] = __ldg((const float*)(Wj + off));
    }
    float2 cur = xr[0];

    #pragma unroll 1
    for (int kb = 0; kb < iters; kb += XR) {
        #pragma unroll
        for (int v = 0; v < XR; ++v) {
            const int k = k0 + kb + v;
            const int u = v & (PD - 1);
            float2 nxt = xr[(v + 1) & (XR - 1)];   // xi[k+1], in registers
            float  w   = wbuf[u];                   // W[row(xi[k])], issued k-PD
            // prefetch weight for iter k+PD; address LDS'd >= 7 iters ago
            unsigned poff = __float_as_uint(xr[(v + PD) & (XR - 1)].y);
            wbuf[u] = __ldg((const float*)(Wj + poff));

            // refill dead slots (v-1, v) with xi[k+15], xi[k+16] (one LDS.128;
            // base index k0+kb+v+15 is even for odd v -> 16B aligned)
            if (v & 1) {
                float4 t = *reinterpret_cast<const float4*>(&xi[k + XR - 1]);
                xr[v - 1] = make_float2(t.x, t.y);
                xr[v]     = make_float2(t.z, t.w);
            }

            // mirror reference: ws*xs (unfused) then cumsum
            wi_cum = __fadd_rn(wi_cum, __fmul_rn(w, cur.x));
            w_cum  = __fadd_rn(w_cum, w);

            if (GATES) {
                float denom = fmaxf(w_cum - 1.0f, 1e-10f);
                // cand >= xs[k]  <=> wi_cum >= xs[k]*denom ; upper gate likewise
                bool valid = (w_cum >= 1.0f)
                           & (wi_cum >= __fmul_rn(cur.x, denom))
                           & (wi_cum <= __fmul_rn(nxt.x, denom));
                const int s = v & (NB - 1);
                bool better = valid
                            & (__fmul_rn(wi_cum, bden[s]) < __fmul_rn(bnum[s], denom));
                if (better) { bnum[s] = wi_cum; bden[s] = denom; }
            }
            cur = nxt;
        }
    }
}

__global__ __launch_bounds__(THREADS, 1)
void snn_layer_kernel(const float* __restrict__ layer_in,
                      const float* __restrict__ weight,
                      const float* __restrict__ delay,
                      float* __restrict__ out)
{
    __shared__ unsigned long long sbuf[NSORT];    // 8 KB sort buffer
    __shared__ __align__(16) float2 xi[XI_SIZE];  // (sorted value, byte-offset bits)
    __shared__ float2 cbest[J_PER_BLOCK];         // chunk0 (num, den) per j-lane
    __shared__ int s_pos;                         // insertion position of appended 1.0

    const int tid   = threadIdx.x;
    const int jl    = tid & (J_PER_BLOCK - 1);    // j lane within block
    const int chunk = tid >> 8;                   // 0: k in [0,672)  1: k in [672,1025)
    const int b     = blockIdx.x >> 1;
    const int j     = (blockIdx.x & 1) * J_PER_BLOCK + jl;

    if (tid == 0) s_pos = 0;
    __syncthreads();

    // ---- Phase 1: keys = (float_bits(x) << 32) | (index << 11) ----
    // x >= 0 so float-bit order == value order; (index<<11) keeps jnp.argsort's
    // stable tie-break and directly encodes the weight-row byte offset.
    // count(x <= 1.0) = stable insertion position of appended (1.0, idx=1024).
    const float* lin = layer_in + (size_t)b * IN_SIZE;
    int cnt = 0;
    for (int i = tid; i < NSORT; i += THREADS) {
        float d  = delay[i];
        float xv = lin[i] * expf(fmaxf(d, 0.0f));   // accurate exp, matches jnp
        cnt += (xv <= 1.0f);
        sbuf[i] = ((unsigned long long)__float_as_uint(xv) << 32)
                | (unsigned)(i << 11);
    }
    if (cnt) atomicAdd(&s_pos, cnt);
    __syncthreads();

    // ---- Phase 2: bitonic sort (ascending), canonical indexing ----
    // 512 threads = exactly NSORT/2 compare-exchanges per step; no idle lanes.
    for (int k = 2; k <= NSORT; k <<= 1) {
        for (int jj = k >> 1; jj > 0; jj >>= 1) {
            int i = ((tid & ~(jj - 1)) << 1) | (tid & (jj - 1));
            int p = i | jj;
            bool up = ((i & k) == 0);
            unsigned long long a = sbuf[i];
            unsigned long long c = sbuf[p];
            if ((a > c) == up) { sbuf[i] = c; sbuf[p] = a; }
            __syncthreads();
        }
    }

    // ---- Phase 3: unpack with insertion of (1.0, idx=1024) + pad ----
    const int pos = s_pos;
    for (int p = tid; p < NSORT; p += THREADS) {
        unsigned long long key = sbuf[p];
        int dest = p + (p >= pos);
        xi[dest] = make_float2(__uint_as_float((unsigned)(key >> 32)),
                               __uint_as_float((unsigned)(key & 0xffffffffu)));
    }
    if (tid == 0) xi[pos] = make_float2(1.0f, __uint_as_float(1024u << 11));
    if (NP1 + tid < XI_SIZE) xi[NP1 + tid] = make_float2(MAX_SPIKE_TIME, 0.0f);
    __syncthreads();

    // ---- Phase 4: k-split scan, slot-private fraction min ----
    const char* Wj = (const char*)(weight + j);
    float w_cum = 0.0f, wi_cum = 0.0f;
    float bnum[NB], bden[NB];
    #pragma unroll
    for (int u = 0; u < NB; ++u) { bnum[u] = MAX_SPIKE_TIME; bden[u] = 1.0f; }

    if (chunk == 0) {
        // gated scan over [0, CHUNK0)
        scan_range<true>(xi, Wj, 0, CHUNK0, w_cum, wi_cum, bnum, bden);
        float bn = bnum[0], bd = bden[0];
        #pragma unroll
        for (int u = 1; u < NB; ++u)
            if (__fmul_rn(bnum[u], bd) < __fmul_rn(bn, bden[u])) { bn = bnum[u]; bd = bden[u]; }
        cbest[jl] = make_float2(bn, bd);
        __syncthreads();
    } else {
        // epilogue weight (k=1024) prefetched now, hidden behind the scan
        unsigned off1024 = __float_as_uint(xi[IN_SIZE].y);
        float we = __ldg((const float*)(Wj + off1024));

        // prefix over [0, CHUNK0): sequential order => accumulators
        // bit-identical to chunk0's finals; then gated scan over [CHUNK0, 1024)
        scan_range<false>(xi, Wj, 0, CHUNK0, w_cum, wi_cum, bnum, bden);
        scan_range<true>(xi, Wj, CHUNK0, IN_SIZE - CHUNK0, w_cum, wi_cum, bnum, bden);

        // epilogue: k = 1024 (sentinel gate on the right)
        {
            float2 cur = xi[IN_SIZE];
            float2 nxt = xi[NP1];
            wi_cum = __fadd_rn(wi_cum, __fmul_rn(we, cur.x));
            w_cum  = __fadd_rn(w_cum, we);
            float denom = fmaxf(w_cum - 1.0f, 1e-10f);
            bool valid = (w_cum >= 1.0f)
                       & (wi_cum >= __fmul_rn(cur.x, denom))
                       & (wi_cum <= __fmul_rn(nxt.x, denom));
            bool better = valid
                        & (__fmul_rn(wi_cum, bden[0]) < __fmul_rn(bnum[0], denom));
            if (better) { bnum[0] = wi_cum; bden[0] = denom; }
        }

        __syncthreads();

        // merge own slots, then combine with chunk0's best and write out
        float bn = bnum[0], bd = bden[0];
        #pragma unroll
        for (int u = 1; u < NB; ++u)
            if (__fmul_rn(bnum[u], bd) < __fmul_rn(bn, bden[u])) { bn = bnum[u]; bd = bden[u]; }
        float2 cb = cbest[jl];
        if (__fmul_rn(cb.x, bd) < __fmul_rn(bn, cb.y)) { bn = cb.x; bd = cb.y; }

        out[(size_t)b * OUT_SIZE + j] = bn / bd;   // one exact IEEE division
    }
}

extern "C" void kernel_launch(void* const* d_in, const int* in_sizes, int n_in,
                              void* d_out, int out_size)
{
    const float* layer_in = (const float*)d_in[0];  // (64, 1024)
    const float* weight   = (const float*)d_in[1];  // (1025, 512)
    const float* delay    = (const float*)d_in[2];  // (1024,)
    float* out = (float*)d_out;                     // (64, 512)

    dim3 grid(B_SIZE * (OUT_SIZE / J_PER_BLOCK));   // 128 blocks
    dim3 block(THREADS);                            // 512 threads
    snn_layer_kernel<<<grid, block>>>(layer_in, weight, delay, out);
}